// round 5
// baseline (speedup 1.0000x reference)
#include <cuda_runtime.h>
#include <cuda_bf16.h>

typedef unsigned long long ull;

#define B_  4
#define C_  128
#define H_  128
#define W_  128
#define HW_ (H_*W_)
#define CHW_ (C_*HW_)

// -------- scratch (device globals; no allocation allowed) --------
__device__ float g_xT[B_*HW_*C_];       // x transposed to [B,H,W,C]  (32 MB)
__device__ float g_off[B_*18*HW_];      // offset conv output [B,18,H,W]
__device__ float g_wK[9*C_*C_];         // w_def reordered to [k][c][o]

// ---------------- helpers ----------------
__device__ __forceinline__ void ffma2(ull &d, ull a, ull b) {
    asm("fma.rn.f32x2 %0, %1, %2, %0;" : "+l"(d) : "l"(a), "l"(b));
}
__device__ __forceinline__ ull packdup(float s) {
    ull r; unsigned int u = __float_as_uint(s);
    asm("mov.b64 %0, {%1, %1};" : "=l"(r) : "r"(u));
    return r;
}
__device__ __forceinline__ void unpack2(ull v, float &lo, float &hi) {
    asm("mov.b64 {%0, %1}, %2;" : "=f"(lo), "=f"(hi) : "l"(v));
}

// ---------------- 1. transpose x: [B,C,H,W] -> [B,H,W,C] ----------------
__global__ void transpose_k(const float* __restrict__ x) {
    __shared__ float t[32][33];
    int b = blockIdx.z;
    int c0 = blockIdx.y * 32;
    int s0 = blockIdx.x * 32;
    int tx = threadIdx.x, ty = threadIdx.y;
    const float* xb = x + (size_t)b * CHW_;
#pragma unroll
    for (int i = 0; i < 4; ++i)
        t[ty + i*8][tx] = xb[(c0 + ty + i*8) * HW_ + s0 + tx];
    __syncthreads();
    float* xtb = g_xT + (size_t)b * CHW_;
#pragma unroll
    for (int i = 0; i < 4; ++i)
        xtb[(s0 + ty + i*8) * C_ + c0 + tx] = t[tx][ty + i*8];
}

// ---------------- 2. reorder w_def[o][c][3][3] -> wK[k][c][o] ----------------
__global__ void reorder_w(const float* __restrict__ w_def) {
    int idx = blockIdx.x * 256 + threadIdx.x;
    if (idx < 9 * C_ * C_) {
        int k = idx / (C_ * C_);
        int r = idx - k * (C_ * C_);
        int c = r >> 7;
        int o = r & 127;
        g_wK[idx] = w_def[(o * C_ + c) * 9 + k];
    }
}

// ---------------- 3. offset conv: 3x3, 18 out channels ----------------
__global__ void __launch_bounds__(128, 2)
offset_conv(const float* __restrict__ x, const float* __restrict__ w_off,
            const float* __restrict__ b_off) {
    extern __shared__ float sWo[];           // 18*1152 floats
    const int tid = threadIdx.x;
    const int h = blockIdx.x;
    const int b = blockIdx.y;
    for (int i = tid; i < 18 * 1152; i += 128) sWo[i] = w_off[i];
    __syncthreads();

    const int w = tid;
    float acc[18];
#pragma unroll
    for (int o = 0; o < 18; ++o) acc[o] = 0.f;

    for (int c = 0; c < C_; ++c) {
        const float* base = x + ((size_t)(b * C_ + c)) * HW_;
#pragma unroll
        for (int ky = 0; ky < 3; ++ky) {
            int yy = h + ky - 1;
            if (yy < 0 || yy >= H_) continue;
            const float* row = base + yy * W_;
#pragma unroll
            for (int kx = 0; kx < 3; ++kx) {
                int xx = w + kx - 1;
                float v = (xx >= 0 && xx < W_) ? __ldg(&row[xx]) : 0.f;
                const float* wp = sWo + c * 9 + ky * 3 + kx;
#pragma unroll
                for (int o = 0; o < 18; ++o) acc[o] += v * wp[o * 1152];
            }
        }
    }
#pragma unroll
    for (int o = 0; o < 18; ++o)
        g_off[((b * 18 + o) * H_ + h) * W_ + w] = acc[o] + __ldg(&b_off[o]);
}

// ---------------- 4. main: gather + GEMM + attention gate ----------------
// Block: 64 positions (half a row) x 128 outputs. 256 threads.
// Smem: sW = wK[k] tile (128c x 128o, 64KB), sS = gathered samples
//       [pos][c] pitch 132 (33KB). Epilogue restages into sW for coalesced out.
#define SPITCH 132
__global__ void __launch_bounds__(256, 2)
deform_main(const float* __restrict__ b_def, const float* __restrict__ w_attn,
            const float* __restrict__ b_attn, float* __restrict__ out) {
    extern __shared__ float smem[];
    float* sW = smem;                 // 16384 floats
    float* sS = smem + 16384;         // 64*SPITCH floats
    __shared__ float sGate[64];

    const int tid = threadIdx.x;
    const int b  = blockIdx.z;
    const int h  = blockIdx.y;
    const int w0 = blockIdx.x * 64;

    const int g = tid & 15;   // output group: outputs g*8 .. g*8+7
    const int q = tid >> 4;   // position group: positions q*4 .. q*4+3

    const int posi  = tid >> 3;   // gather: position within 32-pos pass
    const int lane8 = tid & 7;    // gather: 16-channel slice

    ull acc[4][4];
#pragma unroll
    for (int i = 0; i < 4; ++i)
#pragma unroll
        for (int j = 0; j < 4; ++j) acc[i][j] = 0ull;

    for (int k = 0; k < 9; ++k) {
        __syncthreads();
        // ---- load wK[k] into smem (coalesced float4) ----
        {
            const float4* wg = reinterpret_cast<const float4*>(g_wK + k * 16384);
            float4* sW4 = reinterpret_cast<float4*>(sW);
#pragma unroll
            for (int i = 0; i < 16; ++i) sW4[tid + 256 * i] = wg[tid + 256 * i];
        }
        // ---- gather bilinear samples into sS[pos][c] ----
        const int ky = k / 3, kx = k - ky * 3;
#pragma unroll
        for (int pass = 0; pass < 2; ++pass) {
            int p  = pass * 32 + posi;
            int ww = w0 + p;
            float dy = g_off[((b * 18 + 2 * k    ) * H_ + h) * W_ + ww];
            float dx = g_off[((b * 18 + 2 * k + 1) * H_ + h) * W_ + ww];
            float ys = (float)(h  - 1 + ky) + dy;
            float xs = (float)(ww - 1 + kx) + dx;
            int y0 = __float2int_rd(ys);
            int x0 = __float2int_rd(xs);
            float wy = ys - (float)y0;
            float wx = xs - (float)x0;
            float tw0 = (1.f - wy) * (1.f - wx);
            float tw1 = (1.f - wy) * wx;
            float tw2 = wy * (1.f - wx);
            float tw3 = wy * wx;
            float twA[4] = {tw0, tw1, tw2, tw3};
            int   yyA[4] = {y0, y0, y0 + 1, y0 + 1};
            int   xxA[4] = {x0, x0 + 1, x0, x0 + 1};

            float4 v0 = {0,0,0,0}, v1 = {0,0,0,0}, v2 = {0,0,0,0}, v3 = {0,0,0,0};
#pragma unroll
            for (int t = 0; t < 4; ++t) {
                int yy = yyA[t], xx = xxA[t];
                if (yy >= 0 && yy < H_ && xx >= 0 && xx < W_) {
                    const float4* rp = reinterpret_cast<const float4*>(
                        g_xT + (((b * H_ + yy) * W_ + xx) << 7)) + lane8 * 4;
                    float wt = twA[t];
                    float4 r;
                    r = __ldg(rp + 0); v0.x += wt*r.x; v0.y += wt*r.y; v0.z += wt*r.z; v0.w += wt*r.w;
                    r = __ldg(rp + 1); v1.x += wt*r.x; v1.y += wt*r.y; v1.z += wt*r.z; v1.w += wt*r.w;
                    r = __ldg(rp + 2); v2.x += wt*r.x; v2.y += wt*r.y; v2.z += wt*r.z; v2.w += wt*r.w;
                    r = __ldg(rp + 3); v3.x += wt*r.x; v3.y += wt*r.y; v3.z += wt*r.z; v3.w += wt*r.w;
                }
            }
            float4* sp = reinterpret_cast<float4*>(sS + p * SPITCH + lane8 * 16);
            sp[0] = v0; sp[1] = v1; sp[2] = v2; sp[3] = v3;
        }
        __syncthreads();

        // ---- FFMA2 micro-GEMM: acc[opair][p] += wK[k][c][o..o+1] * s[p][c] ----
        const float* wbase = sW + g * 8;
        const float* sbase = sS + (q * 4) * SPITCH;
#pragma unroll 4
        for (int c = 0; c < 128; ++c) {
            const float* wr = wbase + c * 128;
            ull wv0 = *reinterpret_cast<const ull*>(wr + 0);
            ull wv1 = *reinterpret_cast<const ull*>(wr + 2);
            ull wv2 = *reinterpret_cast<const ull*>(wr + 4);
            ull wv3 = *reinterpret_cast<const ull*>(wr + 6);
            ull s0 = packdup(sbase[0 * SPITCH + c]);
            ull s1 = packdup(sbase[1 * SPITCH + c]);
            ull s2 = packdup(sbase[2 * SPITCH + c]);
            ull s3 = packdup(sbase[3 * SPITCH + c]);
            ffma2(acc[0][0], wv0, s0); ffma2(acc[1][0], wv1, s0);
            ffma2(acc[2][0], wv2, s0); ffma2(acc[3][0], wv3, s0);
            ffma2(acc[0][1], wv0, s1); ffma2(acc[1][1], wv1, s1);
            ffma2(acc[2][1], wv2, s1); ffma2(acc[3][1], wv3, s1);
            ffma2(acc[0][2], wv0, s2); ffma2(acc[1][2], wv1, s2);
            ffma2(acc[2][2], wv2, s2); ffma2(acc[3][2], wv3, s2);
            ffma2(acc[0][3], wv0, s3); ffma2(acc[1][3], wv1, s3);
            ffma2(acc[2][3], wv2, s3); ffma2(acc[3][3], wv3, s3);
        }
    }

    // ---- epilogue: bias -> stage[o][pos] in smem ----
    __syncthreads();
    float* stage = sW;   // 128*64 floats, fits in sW region
#pragma unroll
    for (int op = 0; op < 4; ++op) {
        int o = g * 8 + op * 2;
        float bl = __ldg(&b_def[o]);
        float bh = __ldg(&b_def[o + 1]);
#pragma unroll
        for (int p = 0; p < 4; ++p) {
            float lo, hi;
            unpack2(acc[op][p], lo, hi);
            int pos = q * 4 + p;
            stage[o * 64 + pos]       = lo + bl;
            stage[(o + 1) * 64 + pos] = hi + bh;
        }
    }
    __syncthreads();

    // ---- attention: attn[pos] = sum_o stage[o][pos]*w_attn[o] + b_attn ----
    if (tid < 64) {
        float a = 0.f;
#pragma unroll 8
        for (int o = 0; o < 128; ++o)
            a += stage[o * 64 + tid] * __ldg(&w_attn[o]);
        a += __ldg(&b_attn[0]);
        sGate[tid] = 1.f / (1.f + expf(-a));
    }
    __syncthreads();

    // ---- gate + relu + coalesced float4 store ----
    const float4* st4 = reinterpret_cast<const float4*>(stage);
#pragma unroll
    for (int i = 0; i < 8; ++i) {
        int idx = tid + i * 256;       // float4 index, 2048 total
        int o   = idx >> 4;
        int pf  = (idx & 15) << 2;     // position (multiple of 4)
        float4 v = st4[idx];
        v.x = fmaxf(v.x * sGate[pf + 0], 0.f);
        v.y = fmaxf(v.y * sGate[pf + 1], 0.f);
        v.z = fmaxf(v.z * sGate[pf + 2], 0.f);
        v.w = fmaxf(v.w * sGate[pf + 3], 0.f);
        float* gp = out + (((size_t)(b * C_ + o)) * H_ + h) * W_ + w0 + pf;
        *reinterpret_cast<float4*>(gp) = v;
    }
}

// ---------------- launch ----------------
extern "C" void kernel_launch(void* const* d_in, const int* in_sizes, int n_in,
                              void* d_out, int out_size) {
    const float* x      = (const float*)d_in[0];
    const float* w_off  = (const float*)d_in[1];
    const float* b_off  = (const float*)d_in[2];
    const float* w_def  = (const float*)d_in[3];
    const float* b_def  = (const float*)d_in[4];
    const float* w_attn = (const float*)d_in[5];
    const float* b_attn = (const float*)d_in[6];
    float* out = (float*)d_out;

    const int offc_smem = 18 * 1152 * 4;                 // 82944 B
    const int main_smem = (16384 + 64 * SPITCH) * 4;     // 99328 B
    cudaFuncSetAttribute(offset_conv, cudaFuncAttributeMaxDynamicSharedMemorySize, offc_smem);
    cudaFuncSetAttribute(deform_main, cudaFuncAttributeMaxDynamicSharedMemorySize, main_smem);

    transpose_k<<<dim3(HW_ / 32, C_ / 32, B_), dim3(32, 8)>>>(x);
    reorder_w<<<(9 * C_ * C_ + 255) / 256, 256>>>(w_def);
    offset_conv<<<dim3(H_, B_), 128, offc_smem>>>(x, w_off, b_off);
    deform_main<<<dim3(2, H_, B_), 256, main_smem>>>(b_def, w_attn, b_attn, out);
}

// round 8
// speedup vs baseline: 1.2576x; 1.2576x over previous
#include <cuda_runtime.h>
#include <cuda_bf16.h>

typedef unsigned long long ull;

#define B_  4
#define C_  128
#define H_  128
#define W_  128
#define HW_ (H_*W_)
#define CHW_ (C_*HW_)

// -------- scratch (device globals; no allocation allowed) --------
__device__ float g_xT[B_*HW_*C_];       // x transposed to [B,H,W,C]  (32 MB)
__device__ float g_off[B_*18*HW_];      // offset conv output [B,18,H,W]
__device__ float g_wK[9*C_*C_];         // w_def reordered to [k][c][o]
__device__ float g_wO[C_*9*18];         // w_off reordered to [c][tap][o]

// ---------------- helpers ----------------
__device__ __forceinline__ void ffma2(ull &d, ull a, ull b) {
    asm("fma.rn.f32x2 %0, %1, %2, %0;" : "+l"(d) : "l"(a), "l"(b));
}
__device__ __forceinline__ ull packdup(float s) {
    ull r; unsigned int u = __float_as_uint(s);
    asm("mov.b64 %0, {%1, %1};" : "=l"(r) : "r"(u));
    return r;
}
__device__ __forceinline__ ull pack2(float lo, float hi) {
    ull r;
    asm("mov.b64 %0, {%1, %2};" : "=l"(r) : "f"(lo), "f"(hi));
    return r;
}
__device__ __forceinline__ void unpack2(ull v, float &lo, float &hi) {
    asm("mov.b64 {%0, %1}, %2;" : "=f"(lo), "=f"(hi) : "l"(v));
}

// ---------------- 1. transpose x: [B,C,H,W] -> [B,H,W,C] ----------------
__global__ void transpose_k(const float* __restrict__ x) {
    __shared__ float t[32][33];
    int b = blockIdx.z;
    int c0 = blockIdx.y * 32;
    int s0 = blockIdx.x * 32;
    int tx = threadIdx.x, ty = threadIdx.y;
    const float* xb = x + (size_t)b * CHW_;
#pragma unroll
    for (int i = 0; i < 4; ++i)
        t[ty + i*8][tx] = xb[(c0 + ty + i*8) * HW_ + s0 + tx];
    __syncthreads();
    float* xtb = g_xT + (size_t)b * CHW_;
#pragma unroll
    for (int i = 0; i < 4; ++i)
        xtb[(s0 + ty + i*8) * C_ + c0 + tx] = t[tx][ty + i*8];
}

// ---------------- 2a. reorder w_def[o][c][3][3] -> wK[k][c][o] ----------------
__global__ void reorder_w(const float* __restrict__ w_def) {
    int idx = blockIdx.x * 256 + threadIdx.x;
    if (idx < 9 * C_ * C_) {
        int k = idx / (C_ * C_);
        int r = idx - k * (C_ * C_);
        int c = r >> 7;
        int o = r & 127;
        g_wK[idx] = w_def[(o * C_ + c) * 9 + k];
    }
}

// ---------------- 2b. reorder w_off[o][c][3][3] -> wO[c][tap][o] ----------------
__global__ void reorder_wo(const float* __restrict__ w_off) {
    int idx = blockIdx.x * 256 + threadIdx.x;
    if (idx < C_ * 9 * 18) {
        int c = idx / 162;
        int r = idx - c * 162;
        int t = r / 18;
        int o = r - t * 18;
        g_wO[idx] = w_off[(o * C_ + c) * 9 + t];
    }
}

// ---------------- 3. offset conv: 3x3, 18 out channels (f32x2, 4 px/thread) ---
// Block: 64 threads, 2 rows x 128 cols. Thread: row r=tid>>5, cols cb+{0,32,64,96}.
// Weights staged in smem [c][tap][18]; x rows (4) staged per channel.
__global__ void __launch_bounds__(64, 2)
offset_conv(const float* __restrict__ x, const float* __restrict__ b_off) {
    extern __shared__ float sm[];
    float* sWo = sm;            // 20736 floats
    float* sX  = sm + 20736;    // 4*128 floats

    const int tid = threadIdx.x;
    const int h0  = blockIdx.x * 2;
    const int b   = blockIdx.y;

    // stage weights (once per block)
    {
        const float4* src = reinterpret_cast<const float4*>(g_wO);
        float4* dst = reinterpret_cast<float4*>(sWo);
        for (int i = tid; i < 5184; i += 64) dst[i] = src[i];
    }

    const int r  = tid >> 5;      // 0..1 -> row h0+r
    const int cb = tid & 31;      // pixel cols cb + {0,32,64,96}
    const int h  = h0 + r;

    ull acc[9][4];
#pragma unroll
    for (int o9 = 0; o9 < 9; ++o9)
#pragma unroll
        for (int p = 0; p < 4; ++p) acc[o9][p] = 0ull;

    for (int c = 0; c < C_; ++c) {
        __syncthreads();
        // stage 4 rows (h0-1 .. h0+2) of channel c
        for (int i = tid; i < 128; i += 64) {
            int rr = i >> 5, c4 = i & 31;
            int yy = h0 - 1 + rr;
            float4 v = {0.f, 0.f, 0.f, 0.f};
            if (yy >= 0 && yy < H_)
                v = __ldg(reinterpret_cast<const float4*>(
                        x + ((size_t)(b * C_ + c) * H_ + yy) * W_) + c4);
            reinterpret_cast<float4*>(sX)[i] = v;
        }
        __syncthreads();

#pragma unroll
        for (int ky = 0; ky < 3; ++ky) {
            const float* sr = sX + (r + ky) * W_;
            float xv[4][3];
#pragma unroll
            for (int p = 0; p < 4; ++p) {
                int wc = cb + p * 32;
                xv[p][0] = (wc > 0)   ? sr[wc - 1] : 0.f;
                xv[p][1] = sr[wc];
                xv[p][2] = (wc < 127) ? sr[wc + 1] : 0.f;
            }
#pragma unroll
            for (int kx = 0; kx < 3; ++kx) {
                const ull* wp = reinterpret_cast<const ull*>(
                    sWo + (c * 9 + ky * 3 + kx) * 18);
                ull wv[9];
#pragma unroll
                for (int o9 = 0; o9 < 9; ++o9) wv[o9] = wp[o9];
#pragma unroll
                for (int p = 0; p < 4; ++p) {
                    ull xd = packdup(xv[p][kx]);
#pragma unroll
                    for (int o9 = 0; o9 < 9; ++o9) ffma2(acc[o9][p], wv[o9], xd);
                }
            }
        }
    }

#pragma unroll
    for (int o9 = 0; o9 < 9; ++o9) {
        float b0 = __ldg(&b_off[2 * o9]);
        float b1 = __ldg(&b_off[2 * o9 + 1]);
#pragma unroll
        for (int p = 0; p < 4; ++p) {
            float lo, hi;
            unpack2(acc[o9][p], lo, hi);
            int wc = cb + p * 32;
            g_off[((b * 18 + 2 * o9    ) * H_ + h) * W_ + wc] = lo + b0;
            g_off[((b * 18 + 2 * o9 + 1) * H_ + h) * W_ + wc] = hi + b1;
        }
    }
}

// ---------------- 4. main: gather + GEMM + attention gate ----------------
// Block: 128 threads, tile 128 outputs x 64 positions. Thread: 8o x 8p.
//   tx = tid&15 : outputs {tx*4..tx*4+3} and {64+tx*4..+3} (contiguous LDS.128,
//                 conflict-free per quarter-warp)
//   ty = tid>>4 : positions {ty + 8j}, j=0..7 (s-broadcast pairs land on
//                 different banks: addr delta = SPITCH, SPITCH%32 = 4)
#define SPITCH 132
__global__ void __launch_bounds__(128, 2)
deform_main(const float* __restrict__ b_def, const float* __restrict__ w_attn,
            const float* __restrict__ b_attn, float* __restrict__ out) {
    extern __shared__ float smem[];
    float* sW = smem;                 // 16384 floats
    float* sS = smem + 16384;         // 64*SPITCH floats
    __shared__ float sGate[64];

    const int tid = threadIdx.x;
    const int b  = blockIdx.z;
    const int h  = blockIdx.y;
    const int w0 = blockIdx.x * 64;

    const int tx = tid & 15;
    const int ty = tid >> 4;

    const int half = tid >> 6;    // gather: 64-channel half
    const int posi = tid & 63;    // gather: position

    ull acc[4][8];
#pragma unroll
    for (int i = 0; i < 4; ++i)
#pragma unroll
        for (int j = 0; j < 8; ++j) acc[i][j] = 0ull;

    const float* offbase = g_off + (size_t)b * 18 * HW_ + h * W_ + w0;

    for (int k = 0; k < 9; ++k) {
        __syncthreads();
        // ---- stage wK[k] (coalesced float4) ----
        {
            const float4* wg = reinterpret_cast<const float4*>(g_wK + k * 16384);
            float4* sW4 = reinterpret_cast<float4*>(sW);
#pragma unroll
            for (int i = 0; i < 32; ++i) sW4[tid + 128 * i] = wg[tid + 128 * i];
        }
        // ---- gather bilinear samples: thread = (position, channel-half) ----
        {
            const int ky = k / 3, kx = k - ky * 3;
            const int ww = w0 + posi;
            float dy = offbase[(2 * k    ) * HW_ + posi];
            float dx = offbase[(2 * k + 1) * HW_ + posi];
            float ys = (float)(h  - 1 + ky) + dy;
            float xs = (float)(ww - 1 + kx) + dx;
            int y0 = __float2int_rd(ys);
            int x0 = __float2int_rd(xs);
            float wy = ys - (float)y0;
            float wx = xs - (float)x0;
            float twA[4] = {(1.f - wy) * (1.f - wx), (1.f - wy) * wx,
                            wy * (1.f - wx),          wy * wx};
            const float* rbase[4];
            bool val[4];
#pragma unroll
            for (int t = 0; t < 4; ++t) {
                int yy = y0 + (t >> 1);
                int xx = x0 + (t & 1);
                val[t] = (yy >= 0 && yy < H_ && xx >= 0 && xx < W_);
                int yc = min(max(yy, 0), H_ - 1);
                int xc = min(max(xx, 0), W_ - 1);
                rbase[t] = g_xT + (((size_t)(b * H_ + yc) * W_ + xc) << 7) + half * 64;
            }
            float* sdst = sS + posi * SPITCH + half * 64;
#pragma unroll
            for (int j = 0; j < 4; ++j) {       // 16-channel chunks
                float4 a0 = {0,0,0,0}, a1 = {0,0,0,0}, a2 = {0,0,0,0}, a3 = {0,0,0,0};
#pragma unroll
                for (int t = 0; t < 4; ++t) {
                    if (val[t]) {
                        const float4* rp = reinterpret_cast<const float4*>(rbase[t]) + j * 4;
                        float wt = twA[t];
                        float4 r;
                        r = __ldg(rp + 0); a0.x += wt*r.x; a0.y += wt*r.y; a0.z += wt*r.z; a0.w += wt*r.w;
                        r = __ldg(rp + 1); a1.x += wt*r.x; a1.y += wt*r.y; a1.z += wt*r.z; a1.w += wt*r.w;
                        r = __ldg(rp + 2); a2.x += wt*r.x; a2.y += wt*r.y; a2.z += wt*r.z; a2.w += wt*r.w;
                        r = __ldg(rp + 3); a3.x += wt*r.x; a3.y += wt*r.y; a3.z += wt*r.z; a3.w += wt*r.w;
                    }
                }
                float4* sp = reinterpret_cast<float4*>(sdst + j * 16);
                sp[0] = a0; sp[1] = a1; sp[2] = a2; sp[3] = a3;
            }
        }
        __syncthreads();

        // ---- FFMA2 micro-GEMM: 8o x 8p per thread ----
        const float* wb = sW + tx * 4;
        const float* sb = sS + ty * SPITCH;
#pragma unroll 2
        for (int c = 0; c < 128; ++c) {
            const float* wr = wb + c * 128;
            float4 wA = *reinterpret_cast<const float4*>(wr);
            float4 wB = *reinterpret_cast<const float4*>(wr + 64);
            ull w0v = pack2(wA.x, wA.y);
            ull w1v = pack2(wA.z, wA.w);
            ull w2v = pack2(wB.x, wB.y);
            ull w3v = pack2(wB.z, wB.w);
            const float* sc = sb + c;
#pragma unroll
            for (int j = 0; j < 8; ++j) {
                ull sv = packdup(sc[(8 * j) * SPITCH]);
                ffma2(acc[0][j], w0v, sv);
                ffma2(acc[1][j], w1v, sv);
                ffma2(acc[2][j], w2v, sv);
                ffma2(acc[3][j], w3v, sv);
            }
        }
    }

    // ---- epilogue: bias -> stage[o][pos] ----
    __syncthreads();
    float* stage = sW;
#pragma unroll
    for (int op = 0; op < 4; ++op) {
        int o = (op < 2) ? (tx * 4 + op * 2) : (64 + tx * 4 + (op - 2) * 2);
        float bl = __ldg(&b_def[o]);
        float bh = __ldg(&b_def[o + 1]);
#pragma unroll
        for (int j = 0; j < 8; ++j) {
            float lo, hi;
            unpack2(acc[op][j], lo, hi);
            int pos = ty + 8 * j;
            stage[o * 64 + pos]       = lo + bl;
            stage[(o + 1) * 64 + pos] = hi + bh;
        }
    }
    __syncthreads();

    // ---- attention gate ----
    if (tid < 64) {
        float a = 0.f;
#pragma unroll 8
        for (int o = 0; o < 128; ++o)
            a += stage[o * 64 + tid] * __ldg(&w_attn[o]);
        a += __ldg(&b_attn[0]);
        sGate[tid] = 1.f / (1.f + expf(-a));
    }
    __syncthreads();

    // ---- gate + relu + coalesced float4 store ----
    const float4* st4 = reinterpret_cast<const float4*>(stage);
#pragma unroll
    for (int i = 0; i < 16; ++i) {
        int idx = tid + i * 128;       // float4 index, 2048 total
        int o   = idx >> 4;
        int pf  = (idx & 15) << 2;
        float4 v = st4[idx];
        v.x = fmaxf(v.x * sGate[pf + 0], 0.f);
        v.y = fmaxf(v.y * sGate[pf + 1], 0.f);
        v.z = fmaxf(v.z * sGate[pf + 2], 0.f);
        v.w = fmaxf(v.w * sGate[pf + 3], 0.f);
        float* gp = out + (((size_t)(b * C_ + o)) * H_ + h) * W_ + w0 + pf;
        *reinterpret_cast<float4*>(gp) = v;
    }
}

// ---------------- launch ----------------
extern "C" void kernel_launch(void* const* d_in, const int* in_sizes, int n_in,
                              void* d_out, int out_size) {
    const float* x      = (const float*)d_in[0];
    const float* w_off  = (const float*)d_in[1];
    const float* b_off  = (const float*)d_in[2];
    const float* w_def  = (const float*)d_in[3];
    const float* b_def  = (const float*)d_in[4];
    const float* w_attn = (const float*)d_in[5];
    const float* b_attn = (const float*)d_in[6];
    float* out = (float*)d_out;

    const int offc_smem = (20736 + 512) * 4;             // 84992 B
    const int main_smem = (16384 + 64 * SPITCH) * 4;     // 99328 B
    cudaFuncSetAttribute(offset_conv, cudaFuncAttributeMaxDynamicSharedMemorySize, offc_smem);
    cudaFuncSetAttribute(deform_main, cudaFuncAttributeMaxDynamicSharedMemorySize, main_smem);

    transpose_k<<<dim3(HW_ / 32, C_ / 32, B_), dim3(32, 8)>>>(x);
    reorder_w<<<(9 * C_ * C_ + 255) / 256, 256>>>(w_def);
    reorder_wo<<<(C_ * 9 * 18 + 255) / 256, 256>>>(w_off);
    offset_conv<<<dim3(H_ / 2, B_), 64, offc_smem>>>(x, b_off);
    deform_main<<<dim3(2, H_, B_), 128, main_smem>>>(b_def, w_attn, b_attn, out);
}

// round 9
// speedup vs baseline: 1.3506x; 1.0740x over previous
#include <cuda_runtime.h>
#include <cuda_bf16.h>

typedef unsigned long long ull;

#define B_  4
#define C_  128
#define H_  128
#define W_  128
#define HW_ (H_*W_)
#define CHW_ (C_*HW_)

// -------- scratch (device globals; no allocation allowed) --------
__device__ float g_xT[B_*HW_*C_];       // x transposed to [B,H,W,C]  (32 MB)
__device__ float g_off[B_*18*HW_];      // offset conv output [B,18,H,W]
__device__ float g_wK[9*C_*C_];         // w_def reordered to [k][c][o]
__device__ float g_wO[C_*9*18];         // w_off reordered to [c][tap][o]

// ---------------- helpers ----------------
__device__ __forceinline__ void ffma2(ull &d, ull a, ull b) {
    asm("fma.rn.f32x2 %0, %1, %2, %0;" : "+l"(d) : "l"(a), "l"(b));
}
__device__ __forceinline__ ull packdup(float s) {
    ull r; unsigned int u = __float_as_uint(s);
    asm("mov.b64 %0, {%1, %1};" : "=l"(r) : "r"(u));
    return r;
}
__device__ __forceinline__ ull pack2(float lo, float hi) {
    ull r;
    asm("mov.b64 %0, {%1, %2};" : "=l"(r) : "f"(lo), "f"(hi));
    return r;
}
__device__ __forceinline__ void unpack2(ull v, float &lo, float &hi) {
    asm("mov.b64 {%0, %1}, %2;" : "=f"(lo), "=f"(hi) : "l"(v));
}

// ---------------- 1. transpose x: [B,C,H,W] -> [B,H,W,C] ----------------
__global__ void transpose_k(const float* __restrict__ x) {
    __shared__ float t[32][33];
    int b = blockIdx.z;
    int c0 = blockIdx.y * 32;
    int s0 = blockIdx.x * 32;
    int tx = threadIdx.x, ty = threadIdx.y;
    const float* xb = x + (size_t)b * CHW_;
#pragma unroll
    for (int i = 0; i < 4; ++i)
        t[ty + i*8][tx] = xb[(c0 + ty + i*8) * HW_ + s0 + tx];
    __syncthreads();
    float* xtb = g_xT + (size_t)b * CHW_;
#pragma unroll
    for (int i = 0; i < 4; ++i)
        xtb[(s0 + ty + i*8) * C_ + c0 + tx] = t[tx][ty + i*8];
}

// ---------------- 2a. reorder w_def[o][c][3][3] -> wK[k][c][o] ----------------
__global__ void reorder_w(const float* __restrict__ w_def) {
    int idx = blockIdx.x * 256 + threadIdx.x;
    if (idx < 9 * C_ * C_) {
        int k = idx / (C_ * C_);
        int r = idx - k * (C_ * C_);
        int c = r >> 7;
        int o = r & 127;
        g_wK[idx] = w_def[(o * C_ + c) * 9 + k];
    }
}

// ---------------- 2b. reorder w_off[o][c][3][3] -> wO[c][tap][o] ----------------
__global__ void reorder_wo(const float* __restrict__ w_off) {
    int idx = blockIdx.x * 256 + threadIdx.x;
    if (idx < C_ * 9 * 18) {
        int c = idx / 162;
        int r = idx - c * 162;
        int t = r / 18;
        int o = r - t * 18;
        g_wO[idx] = w_off[(o * C_ + c) * 9 + t];
    }
}

// ---------------- 3. offset conv: 3x3, 18 out (register-pipelined) -----------
// 64 threads, 2 rows x 128 cols, 4 px/thread. No x smem, no per-channel syncs:
// channel c+1's 36 LDGs are issued before channel c's 324 FFMA2s (double-
// buffered register window) so load latency hides under the FMA block.
__global__ void __launch_bounds__(64, 2)
offset_conv(const float* __restrict__ x, const float* __restrict__ b_off) {
    extern __shared__ float sWo[];           // 20736 floats = [c][tap][18]

    const int tid = threadIdx.x;
    const int h0  = blockIdx.x * 2;
    const int b   = blockIdx.y;

    {
        const float4* src = reinterpret_cast<const float4*>(g_wO);
        float4* dst = reinterpret_cast<float4*>(sWo);
        for (int i = tid; i < 5184; i += 64) dst[i] = src[i];
    }
    __syncthreads();

    const int r  = tid >> 5;
    const int cb = tid & 31;
    const int h  = h0 + r;

    ull acc[9][4];
#pragma unroll
    for (int o9 = 0; o9 < 9; ++o9)
#pragma unroll
        for (int p = 0; p < 4; ++p) acc[o9][p] = 0ull;

    float xv[2][3][4][3];

    auto load_c = [&](int c, float v[3][4][3]) {
        const float* base = x + ((size_t)(b * C_ + c)) * HW_;
#pragma unroll
        for (int ky = 0; ky < 3; ++ky) {
            int yy = h - 1 + ky;
            bool rv = (yy >= 0 && yy < H_);
            const float* row = base + (rv ? yy : 0) * W_;
#pragma unroll
            for (int p = 0; p < 4; ++p) {
                int wc = cb + 32 * p;
                v[ky][p][0] = (rv && wc > 0)   ? __ldg(row + wc - 1) : 0.f;
                v[ky][p][1] = rv               ? __ldg(row + wc)     : 0.f;
                v[ky][p][2] = (rv && wc < 127) ? __ldg(row + wc + 1) : 0.f;
            }
        }
    };

    load_c(0, xv[0]);

    for (int c = 0; c < C_; ++c) {
        int cur = c & 1;
        if (c < C_ - 1) load_c(c + 1, xv[cur ^ 1]);   // prefetch next channel
#pragma unroll
        for (int ky = 0; ky < 3; ++ky) {
#pragma unroll
            for (int kx = 0; kx < 3; ++kx) {
                const ull* wp = reinterpret_cast<const ull*>(
                    sWo + (c * 9 + ky * 3 + kx) * 18);
                ull wv[9];
#pragma unroll
                for (int o9 = 0; o9 < 9; ++o9) wv[o9] = wp[o9];
#pragma unroll
                for (int p = 0; p < 4; ++p) {
                    ull xd = packdup(xv[cur][ky][p][kx]);
#pragma unroll
                    for (int o9 = 0; o9 < 9; ++o9) ffma2(acc[o9][p], wv[o9], xd);
                }
            }
        }
    }

#pragma unroll
    for (int o9 = 0; o9 < 9; ++o9) {
        float b0 = __ldg(&b_off[2 * o9]);
        float b1 = __ldg(&b_off[2 * o9 + 1]);
#pragma unroll
        for (int p = 0; p < 4; ++p) {
            float lo, hi;
            unpack2(acc[o9][p], lo, hi);
            int wc = cb + p * 32;
            g_off[((b * 18 + 2 * o9    ) * H_ + h) * W_ + wc] = lo + b0;
            g_off[((b * 18 + 2 * o9 + 1) * H_ + h) * W_ + wc] = hi + b1;
        }
    }
}

// ---------------- 4. main: pipelined gather + GEMM + attention gate ----------
// Block: 128 threads, tile 128 outputs x 64 positions, thread 8o x 8p.
// Gather for k+1 accumulates in REGISTERS (f32x2) during GEMM(k); stored to
// smem at the top of the next iteration, so gather LDG latency hides under FMA.
#define SPITCH 132
__global__ void __launch_bounds__(128, 2)
deform_main(const float* __restrict__ b_def, const float* __restrict__ w_attn,
            const float* __restrict__ b_attn, float* __restrict__ out) {
    extern __shared__ float smem[];
    float* sW = smem;                 // 16384 floats
    float* sS = smem + 16384;         // 64*SPITCH floats
    __shared__ float sGate[64];

    const int tid = threadIdx.x;
    const int b  = blockIdx.z;
    const int h  = blockIdx.y;
    const int w0 = blockIdx.x * 64;

    const int tx = tid & 15;
    const int ty = tid >> 4;

    const int half = tid >> 6;    // gather: 64-channel half
    const int posi = tid & 63;    // gather: position

    ull acc[4][8];
#pragma unroll
    for (int i = 0; i < 4; ++i)
#pragma unroll
        for (int j = 0; j < 8; ++j) acc[i][j] = 0ull;

    const float* offbase = g_off + (size_t)b * 18 * HW_ + h * W_ + w0;

    ull gv[32];

    auto do_gather = [&](int k) {
        const int ky = k / 3, kx = k - 3 * ky;
        const int ww = w0 + posi;
        float dy = offbase[(2 * k    ) * HW_ + posi];
        float dx = offbase[(2 * k + 1) * HW_ + posi];
        float ys = (float)(h  - 1 + ky) + dy;
        float xs = (float)(ww - 1 + kx) + dx;
        int y0 = __float2int_rd(ys);
        int x0 = __float2int_rd(xs);
        float wy = ys - (float)y0;
        float wx = xs - (float)x0;
        float twA[4] = {(1.f - wy) * (1.f - wx), (1.f - wy) * wx,
                        wy * (1.f - wx),          wy * wx};
#pragma unroll
        for (int j = 0; j < 32; ++j) gv[j] = 0ull;
#pragma unroll
        for (int t = 0; t < 4; ++t) {
            int yy = y0 + (t >> 1);
            int xx = x0 + (t & 1);
            if (yy >= 0 && yy < H_ && xx >= 0 && xx < W_) {
                const ulonglong2* rp = reinterpret_cast<const ulonglong2*>(
                    g_xT + (((size_t)(b * H_ + yy) * W_ + xx) << 7) + half * 64);
                ull wt2 = packdup(twA[t]);
#pragma unroll
                for (int j = 0; j < 16; ++j) {
                    ulonglong2 rr = __ldg(rp + j);
                    ffma2(gv[2 * j    ], wt2, rr.x);
                    ffma2(gv[2 * j + 1], wt2, rr.y);
                }
            }
        }
    };

    do_gather(0);

    for (int k = 0; k < 9; ++k) {
        __syncthreads();                    // sS/sW(k-1) consumed
        // ---- commit gathered regs -> sS (phase-conflict-free 16B stores) ----
        {
            ulonglong2* sp = reinterpret_cast<ulonglong2*>(
                sS + posi * SPITCH + half * 64);
#pragma unroll
            for (int j = 0; j < 16; ++j)
                sp[j] = make_ulonglong2(gv[2 * j], gv[2 * j + 1]);
        }
        // ---- stage wK[k] (coalesced float4) ----
        {
            const float4* wg = reinterpret_cast<const float4*>(g_wK + k * 16384);
            float4* sW4 = reinterpret_cast<float4*>(sW);
#pragma unroll
            for (int i = 0; i < 32; ++i) sW4[tid + 128 * i] = wg[tid + 128 * i];
        }
        __syncthreads();

        if (k < 8) do_gather(k + 1);        // LDGs fly during GEMM below

        // ---- FFMA2 micro-GEMM: 8o x 8p per thread ----
        const float* wb = sW + tx * 4;
        const float* sb = sS + ty * SPITCH;
#pragma unroll 2
        for (int c = 0; c < 128; ++c) {
            const float* wr = wb + c * 128;
            float4 wA = *reinterpret_cast<const float4*>(wr);
            float4 wB = *reinterpret_cast<const float4*>(wr + 64);
            ull w0v = pack2(wA.x, wA.y);
            ull w1v = pack2(wA.z, wA.w);
            ull w2v = pack2(wB.x, wB.y);
            ull w3v = pack2(wB.z, wB.w);
            const float* sc = sb + c;
#pragma unroll
            for (int j = 0; j < 8; ++j) {
                ull sv = packdup(sc[(8 * j) * SPITCH]);
                ffma2(acc[0][j], w0v, sv);
                ffma2(acc[1][j], w1v, sv);
                ffma2(acc[2][j], w2v, sv);
                ffma2(acc[3][j], w3v, sv);
            }
        }
    }

    // ---- epilogue: bias -> stage[o][pos] ----
    __syncthreads();
    float* stage = sW;
#pragma unroll
    for (int op = 0; op < 4; ++op) {
        int o = (op < 2) ? (tx * 4 + op * 2) : (64 + tx * 4 + (op - 2) * 2);
        float bl = __ldg(&b_def[o]);
        float bh = __ldg(&b_def[o + 1]);
#pragma unroll
        for (int j = 0; j < 8; ++j) {
            float lo, hi;
            unpack2(acc[op][j], lo, hi);
            int pos = ty + 8 * j;
            stage[o * 64 + pos]       = lo + bl;
            stage[(o + 1) * 64 + pos] = hi + bh;
        }
    }
    __syncthreads();

    // ---- attention gate ----
    if (tid < 64) {
        float a = 0.f;
#pragma unroll 8
        for (int o = 0; o < 128; ++o)
            a += stage[o * 64 + tid] * __ldg(&w_attn[o]);
        a += __ldg(&b_attn[0]);
        sGate[tid] = 1.f / (1.f + expf(-a));
    }
    __syncthreads();

    // ---- gate + relu + coalesced float4 store ----
    const float4* st4 = reinterpret_cast<const float4*>(stage);
#pragma unroll
    for (int i = 0; i < 16; ++i) {
        int idx = tid + i * 128;
        int o   = idx >> 4;
        int pf  = (idx & 15) << 2;
        float4 v = st4[idx];
        v.x = fmaxf(v.x * sGate[pf + 0], 0.f);
        v.y = fmaxf(v.y * sGate[pf + 1], 0.f);
        v.z = fmaxf(v.z * sGate[pf + 2], 0.f);
        v.w = fmaxf(v.w * sGate[pf + 3], 0.f);
        float* gp = out + (((size_t)(b * C_ + o)) * H_ + h) * W_ + w0 + pf;
        *reinterpret_cast<float4*>(gp) = v;
    }
}

// ---------------- launch ----------------
extern "C" void kernel_launch(void* const* d_in, const int* in_sizes, int n_in,
                              void* d_out, int out_size) {
    const float* x      = (const float*)d_in[0];
    const float* w_off  = (const float*)d_in[1];
    const float* b_off  = (const float*)d_in[2];
    const float* w_def  = (const float*)d_in[3];
    const float* b_def  = (const float*)d_in[4];
    const float* w_attn = (const float*)d_in[5];
    const float* b_attn = (const float*)d_in[6];
    float* out = (float*)d_out;

    const int offc_smem = 20736 * 4;                     // 82944 B
    const int main_smem = (16384 + 64 * SPITCH) * 4;     // 99328 B
    cudaFuncSetAttribute(offset_conv, cudaFuncAttributeMaxDynamicSharedMemorySize, offc_smem);
    cudaFuncSetAttribute(deform_main, cudaFuncAttributeMaxDynamicSharedMemorySize, main_smem);

    transpose_k<<<dim3(HW_ / 32, C_ / 32, B_), dim3(32, 8)>>>(x);
    reorder_w<<<(9 * C_ * C_ + 255) / 256, 256>>>(w_def);
    reorder_wo<<<(C_ * 9 * 18 + 255) / 256, 256>>>(w_off);
    offset_conv<<<dim3(H_ / 2, B_), 64, offc_smem>>>(x, b_off);
    deform_main<<<dim3(2, H_, B_), 128, main_smem>>>(b_def, w_attn, b_attn, out);
}

// round 14
// speedup vs baseline: 1.6425x; 1.2161x over previous
#include <cuda_runtime.h>
#include <cuda_bf16.h>

typedef unsigned long long ull;

#define B_  4
#define C_  128
#define H_  128
#define W_  128
#define HW_ (H_*W_)
#define CHW_ (C_*HW_)
#define PSZ (B_*18*HW_)          // one offset-partial slab

// -------- scratch (device globals; no allocation allowed) --------
__device__ float g_xT[B_*HW_*C_];       // x transposed to [B,H,W,C]  (32 MB)
__device__ float g_off[4*PSZ];          // 4 channel-split partials of offset conv
__device__ float g_wK[9*C_*C_];         // w_def reordered to [k][c][o]
__device__ float g_wO[C_*9*18];         // w_off reordered to [c][tap][o]

// ---------------- helpers ----------------
__device__ __forceinline__ void ffma2(ull &d, ull a, ull b) {
    asm("fma.rn.f32x2 %0, %1, %2, %0;" : "+l"(d) : "l"(a), "l"(b));
}
__device__ __forceinline__ ull packdup(float s) {
    ull r; unsigned int u = __float_as_uint(s);
    asm("mov.b64 %0, {%1, %1};" : "=l"(r) : "r"(u));
    return r;
}
__device__ __forceinline__ ull pack2(float lo, float hi) {
    ull r;
    asm("mov.b64 %0, {%1, %2};" : "=l"(r) : "f"(lo), "f"(hi));
    return r;
}
__device__ __forceinline__ void unpack2(ull v, float &lo, float &hi) {
    asm("mov.b64 {%0, %1}, %2;" : "=f"(lo), "=f"(hi) : "l"(v));
}

// ---------------- 1. transpose x: [B,C,H,W] -> [B,H,W,C] ----------------
__global__ void transpose_k(const float* __restrict__ x) {
    __shared__ float t[32][33];
    int b = blockIdx.z;
    int c0 = blockIdx.y * 32;
    int s0 = blockIdx.x * 32;
    int tx = threadIdx.x, ty = threadIdx.y;
    const float* xb = x + (size_t)b * CHW_;
#pragma unroll
    for (int i = 0; i < 4; ++i)
        t[ty + i*8][tx] = xb[(c0 + ty + i*8) * HW_ + s0 + tx];
    __syncthreads();
    float* xtb = g_xT + (size_t)b * CHW_;
#pragma unroll
    for (int i = 0; i < 4; ++i)
        xtb[(s0 + ty + i*8) * C_ + c0 + tx] = t[tx][ty + i*8];
}

// ---------------- 2a. reorder w_def[o][c][3][3] -> wK[k][c][o] ----------------
__global__ void reorder_w(const float* __restrict__ w_def) {
    int idx = blockIdx.x * 256 + threadIdx.x;
    if (idx < 9 * C_ * C_) {
        int k = idx / (C_ * C_);
        int r = idx - k * (C_ * C_);
        int c = r >> 7;
        int o = r & 127;
        g_wK[idx] = w_def[(o * C_ + c) * 9 + k];
    }
}

// ---------------- 2b. reorder w_off[o][c][3][3] -> wO[c][tap][o] ----------------
__global__ void reorder_wo(const float* __restrict__ w_off) {
    int idx = blockIdx.x * 256 + threadIdx.x;
    if (idx < C_ * 9 * 18) {
        int c = idx / 162;
        int r = idx - c * 162;
        int t = r / 18;
        int o = r - t * 18;
        g_wO[idx] = w_off[(o * C_ + c) * 9 + t];
    }
}

// ---------------- 3. offset conv: 3x3, 18 out, channel-split x4 --------------
// Block: 64 threads, 2 rows x 128 cols, 4 px/thread, 32 channels (split s).
// Partials written to g_off[s]; deform_main sums the 4 partials.
__global__ void __launch_bounds__(64, 6)
offset_conv(const float* __restrict__ x, const float* __restrict__ b_off) {
    extern __shared__ float sWo[];           // 32*9*18 = 5184 floats

    const int tid = threadIdx.x;
    const int s   = blockIdx.x & 3;          // channel split
    const int h0  = (blockIdx.x >> 2) * 2;
    const int b   = blockIdx.y;
    const int c0  = s * 32;

    {
        const float4* src = reinterpret_cast<const float4*>(g_wO + c0 * 162);
        float4* dst = reinterpret_cast<float4*>(sWo);
        for (int i = tid; i < 1296; i += 64) dst[i] = src[i];
    }
    __syncthreads();

    const int r  = tid >> 5;
    const int cb = tid & 31;
    const int h  = h0 + r;

    ull acc[9][4];
#pragma unroll
    for (int o9 = 0; o9 < 9; ++o9)
#pragma unroll
        for (int p = 0; p < 4; ++p) acc[o9][p] = 0ull;

    float xv[2][3][4][3];

    auto load_c = [&](int c, float v[3][4][3]) {
        const float* base = x + ((size_t)(b * C_ + c0 + c)) * HW_;
#pragma unroll
        for (int ky = 0; ky < 3; ++ky) {
            int yy = h - 1 + ky;
            bool rv = (yy >= 0 && yy < H_);
            const float* row = base + (rv ? yy : 0) * W_;
#pragma unroll
            for (int p = 0; p < 4; ++p) {
                int wc = cb + 32 * p;
                v[ky][p][0] = (rv && wc > 0)   ? __ldg(row + wc - 1) : 0.f;
                v[ky][p][1] = rv               ? __ldg(row + wc)     : 0.f;
                v[ky][p][2] = (rv && wc < 127) ? __ldg(row + wc + 1) : 0.f;
            }
        }
    };

    load_c(0, xv[0]);

    for (int c = 0; c < 32; ++c) {
        int cur = c & 1;
        if (c < 31) load_c(c + 1, xv[cur ^ 1]);   // prefetch next channel
#pragma unroll
        for (int ky = 0; ky < 3; ++ky) {
#pragma unroll
            for (int kx = 0; kx < 3; ++kx) {
                const ull* wp = reinterpret_cast<const ull*>(
                    sWo + (c * 9 + ky * 3 + kx) * 18);
                ull wv[9];
#pragma unroll
                for (int o9 = 0; o9 < 9; ++o9) wv[o9] = wp[o9];
#pragma unroll
                for (int p = 0; p < 4; ++p) {
                    ull xd = packdup(xv[cur][ky][p][kx]);
#pragma unroll
                    for (int o9 = 0; o9 < 9; ++o9) ffma2(acc[o9][p], wv[o9], xd);
                }
            }
        }
    }

    float* dst = g_off + (size_t)s * PSZ;
#pragma unroll
    for (int o9 = 0; o9 < 9; ++o9) {
        float b0 = (s == 0) ? __ldg(&b_off[2 * o9])     : 0.f;
        float b1 = (s == 0) ? __ldg(&b_off[2 * o9 + 1]) : 0.f;
#pragma unroll
        for (int p = 0; p < 4; ++p) {
            float lo, hi;
            unpack2(acc[o9][p], lo, hi);
            int wc = cb + p * 32;
            dst[((b * 18 + 2 * o9    ) * H_ + h) * W_ + wc] = lo + b0;
            dst[((b * 18 + 2 * o9 + 1) * H_ + h) * W_ + wc] = hi + b1;
        }
    }
}

// ---------------- 4. main: pipelined COALESCED gather + GEMM + gate ----------
// Block: 128 threads, tile 128 outputs x 64 positions, thread 8o x 8p.
// Gather: 4 passes of (16 positions x 8 lanes); each lane reads interleaved
// float4s so every LDG.128 covers 4x128B contiguous segments (nL=4).
// Gather(k+1) accumulates in registers during GEMM(k).
#define SPITCH 132
__global__ void __launch_bounds__(128, 2)
deform_main(const float* __restrict__ b_def, const float* __restrict__ w_attn,
            const float* __restrict__ b_attn, float* __restrict__ out) {
    extern __shared__ float smem[];
    float* sW = smem;                 // 16384 floats
    float* sS = smem + 16384;         // 64*SPITCH floats
    __shared__ float sGate[64];

    const int tid = threadIdx.x;
    const int b  = blockIdx.z;
    const int h  = blockIdx.y;
    const int w0 = blockIdx.x * 64;

    const int tx = tid & 15;
    const int ty = tid >> 4;

    const int posi8 = tid >> 3;   // gather: position within 16-pos pass
    const int lane8 = tid & 7;    // gather: lane within position

    ull acc[4][8];
#pragma unroll
    for (int i = 0; i < 4; ++i)
#pragma unroll
        for (int j = 0; j < 8; ++j) acc[i][j] = 0ull;

    const float* offbase = g_off + (size_t)b * 18 * HW_ + h * W_ + w0;

    ull gv[32];

    auto do_gather = [&](int k) {
        const int ky = k / 3, kx = k - 3 * ky;
#pragma unroll
        for (int p = 0; p < 4; ++p) {
            const int pos = posi8 + 16 * p;
            const int ww  = w0 + pos;
            int oy = (2 * k) * HW_ + pos - w0 + 0;   // index rel. offbase
            oy = (2 * k) * HW_ + pos;
            int ox = (2 * k + 1) * HW_ + pos;
            float dy = offbase[oy] + offbase[oy + PSZ] +
                       offbase[oy + 2 * PSZ] + offbase[oy + 3 * PSZ];
            float dx = offbase[ox] + offbase[ox + PSZ] +
                       offbase[ox + 2 * PSZ] + offbase[ox + 3 * PSZ];
            float ys = (float)(h  - 1 + ky) + dy;
            float xs = (float)(ww - 1 + kx) + dx;
            int y0 = __float2int_rd(ys);
            int x0 = __float2int_rd(xs);
            float wy = ys - (float)y0;
            float wx = xs - (float)x0;
            float twA[4] = {(1.f - wy) * (1.f - wx), (1.f - wy) * wx,
                            wy * (1.f - wx),          wy * wx};
            ull* g = gv + p * 8;
#pragma unroll
            for (int j = 0; j < 8; ++j) g[j] = 0ull;
#pragma unroll
            for (int t = 0; t < 4; ++t) {
                int yy = y0 + (t >> 1);
                int xx = x0 + (t & 1);
                if (yy >= 0 && yy < H_ && xx >= 0 && xx < W_) {
                    const ulonglong2* rp = reinterpret_cast<const ulonglong2*>(
                        g_xT + (((size_t)(b * H_ + yy) * W_ + xx) << 7));
                    ull wt2 = packdup(twA[t]);
#pragma unroll
                    for (int j = 0; j < 4; ++j) {
                        // lanes 0..7 contiguous within each j-segment (128B)
                        ulonglong2 rr = __ldg(rp + j * 8 + lane8);
                        ffma2(g[2 * j    ], wt2, rr.x);
                        ffma2(g[2 * j + 1], wt2, rr.y);
                    }
                }
            }
        }
    };

    do_gather(0);

    for (int k = 0; k < 9; ++k) {
        __syncthreads();                    // sS/sW(k-1) consumed
        // ---- commit gathered regs -> sS (channel slot = 4*(j*8+lane8)) ----
#pragma unroll
        for (int p = 0; p < 4; ++p) {
            ulonglong2* sp = reinterpret_cast<ulonglong2*>(
                sS + (posi8 + 16 * p) * SPITCH);
#pragma unroll
            for (int j = 0; j < 4; ++j)
                sp[j * 8 + lane8] =
                    make_ulonglong2(gv[p * 8 + 2 * j], gv[p * 8 + 2 * j + 1]);
        }
        // ---- stage wK[k] (coalesced float4) ----
        {
            const float4* wg = reinterpret_cast<const float4*>(g_wK + k * 16384);
            float4* sW4 = reinterpret_cast<float4*>(sW);
#pragma unroll
            for (int i = 0; i < 32; ++i) sW4[tid + 128 * i] = wg[tid + 128 * i];
        }
        __syncthreads();

        if (k < 8) do_gather(k + 1);        // LDGs fly during GEMM below

        // ---- FFMA2 micro-GEMM: 8o x 8p per thread ----
        const float* wb = sW + tx * 4;
        const float* sb = sS + ty * SPITCH;
#pragma unroll 2
        for (int c = 0; c < 128; ++c) {
            const float* wr = wb + c * 128;
            float4 wA = *reinterpret_cast<const float4*>(wr);
            float4 wB = *reinterpret_cast<const float4*>(wr + 64);
            ull w0v = pack2(wA.x, wA.y);
            ull w1v = pack2(wA.z, wA.w);
            ull w2v = pack2(wB.x, wB.y);
            ull w3v = pack2(wB.z, wB.w);
            const float* sc = sb + c;
#pragma unroll
            for (int j = 0; j < 8; ++j) {
                ull sv = packdup(sc[(8 * j) * SPITCH]);
                ffma2(acc[0][j], w0v, sv);
                ffma2(acc[1][j], w1v, sv);
                ffma2(acc[2][j], w2v, sv);
                ffma2(acc[3][j], w3v, sv);
            }
        }
    }

    // ---- epilogue: bias -> stage[o][pos] ----
    __syncthreads();
    float* stage = sW;
#pragma unroll
    for (int op = 0; op < 4; ++op) {
        int o = (op < 2) ? (tx * 4 + op * 2) : (64 + tx * 4 + (op - 2) * 2);
        float bl = __ldg(&b_def[o]);
        float bh = __ldg(&b_def[o + 1]);
#pragma unroll
        for (int j = 0; j < 8; ++j) {
            float lo, hi;
            unpack2(acc[op][j], lo, hi);
            int pos = ty + 8 * j;
            stage[o * 64 + pos]       = lo + bl;
            stage[(o + 1) * 64 + pos] = hi + bh;
        }
    }
    __syncthreads();

    // ---- attention gate ----
    if (tid < 64) {
        float a = 0.f;
#pragma unroll 8
        for (int o = 0; o < 128; ++o)
            a += stage[o * 64 + tid] * __ldg(&w_attn[o]);
        a += __ldg(&b_attn[0]);
        sGate[tid] = 1.f / (1.f + expf(-a));
    }
    __syncthreads();

    // ---- gate + relu + coalesced float4 store ----
    const float4* st4 = reinterpret_cast<const float4*>(stage);
#pragma unroll
    for (int i = 0; i < 16; ++i) {
        int idx = tid + i * 128;
        int o   = idx >> 4;
        int pf  = (idx & 15) << 2;
        float4 v = st4[idx];
        v.x = fmaxf(v.x * sGate[pf + 0], 0.f);
        v.y = fmaxf(v.y * sGate[pf + 1], 0.f);
        v.z = fmaxf(v.z * sGate[pf + 2], 0.f);
        v.w = fmaxf(v.w * sGate[pf + 3], 0.f);
        float* gp = out + (((size_t)(b * C_ + o)) * H_ + h) * W_ + w0 + pf;
        *reinterpret_cast<float4*>(gp) = v;
    }
}

// ---------------- launch ----------------
extern "C" void kernel_launch(void* const* d_in, const int* in_sizes, int n_in,
                              void* d_out, int out_size) {
    const float* x      = (const float*)d_in[0];
    const float* w_off  = (const float*)d_in[1];
    const float* b_off  = (const float*)d_in[2];
    const float* w_def  = (const float*)d_in[3];
    const float* b_def  = (const float*)d_in[4];
    const float* w_attn = (const float*)d_in[5];
    const float* b_attn = (const float*)d_in[6];
    float* out = (float*)d_out;

    const int offc_smem = 5184 * 4;                      // 20736 B
    const int main_smem = (16384 + 64 * SPITCH) * 4;     // 99328 B
    cudaFuncSetAttribute(offset_conv, cudaFuncAttributeMaxDynamicSharedMemorySize, offc_smem);
    cudaFuncSetAttribute(deform_main, cudaFuncAttributeMaxDynamicSharedMemorySize, main_smem);

    transpose_k<<<dim3(HW_ / 32, C_ / 32, B_), dim3(32, 8)>>>(x);
    reorder_w<<<(9 * C_ * C_ + 255) / 256, 256>>>(w_def);
    reorder_wo<<<(C_ * 9 * 18 + 255) / 256, 256>>>(w_off);
    offset_conv<<<dim3((H_ / 2) * 4, B_), 64, offc_smem>>>(x, b_off);
    deform_main<<<dim3(2, H_, B_), 128, main_smem>>>(b_def, w_attn, b_attn, out);
}

// round 17
// speedup vs baseline: 2.3546x; 1.4335x over previous
#include <cuda_runtime.h>
#include <cuda_bf16.h>
#include <cstdint>

typedef unsigned long long ull;

#define B_  4
#define C_  128
#define H_  128
#define W_  128
#define HW_ (H_*W_)
#define CHW_ (C_*HW_)
#define PSZ (B_*18*HW_)          // one offset-partial slab

// bf16 tile geometry (padded pitch for conflict-free ldmatrix)
#define KP    136                // bf16 elements per row (128 + 8 pad)
#define KPB   272                // bytes per row
#define TILEB (128*KPB)          // 34816 B: one 128x128 bf16 tile (padded)
#define TAPB  (2*TILEB)          // hi + lo per tap = 69632 B

// smem layout for deform_main
#define SA_HI  0
#define SA_LO  TILEB
#define SB0    (2*TILEB)                 // two tap buffers follow
#define SMEMSZ (2*TILEB + 2*TAPB)       // 208896 B

// -------- scratch (device globals; no allocation allowed) --------
__device__ float g_xT[B_*HW_*C_];             // x transposed to [B,H,W,C] (32 MB)
__device__ float g_off[4*PSZ];                // 4 channel-split partials of offset conv
__device__ float g_wO[C_*9*18];               // w_off reordered to [c][tap][o]
__device__ __nv_bfloat16 g_wB[9*2*128*KP];    // w_def hi/lo, padded [k][s][n][c]

// ---------------- scalar helpers ----------------
__device__ __forceinline__ void ffma2(ull &d, ull a, ull b) {
    asm("fma.rn.f32x2 %0, %1, %2, %0;" : "+l"(d) : "l"(a), "l"(b));
}
__device__ __forceinline__ ull packdup(float s) {
    ull r; unsigned int u = __float_as_uint(s);
    asm("mov.b64 %0, {%1, %1};" : "=l"(r) : "r"(u));
    return r;
}
__device__ __forceinline__ void unpack2(ull v, float &lo, float &hi) {
    asm("mov.b64 {%0, %1}, %2;" : "=f"(lo), "=f"(hi) : "l"(v));
}
__device__ __forceinline__ uint32_t bf16x2_of(float lo, float hi) {
    uint32_t r;
    asm("cvt.rn.bf16x2.f32 %0, %1, %2;" : "=r"(r) : "f"(hi), "f"(lo));
    return r;   // lower 16 bits = bf16(lo), upper = bf16(hi)
}

// ---------------- tensor-path helpers (all baseline PTX, no 'a' feats) ------
__device__ __forceinline__ uint32_t smem_u32(const void* p) {
    uint32_t a;
    asm("{ .reg .u64 t; cvta.to.shared.u64 t, %1; cvt.u32.u64 %0, t; }"
        : "=r"(a) : "l"(p));
    return a;
}
__device__ __forceinline__ void ldmx4(uint32_t* r, uint32_t addr) {
    asm volatile("ldmatrix.sync.aligned.m8n8.x4.shared.b16 {%0,%1,%2,%3}, [%4];"
        : "=r"(r[0]), "=r"(r[1]), "=r"(r[2]), "=r"(r[3]) : "r"(addr));
}
__device__ __forceinline__ void mma_bf16(float* d, const uint32_t* a,
                                         uint32_t b0, uint32_t b1) {
    asm volatile("mma.sync.aligned.m16n8k16.row.col.f32.bf16.bf16.f32 "
        "{%0,%1,%2,%3}, {%4,%5,%6,%7}, {%8,%9}, {%0,%1,%2,%3};"
        : "+f"(d[0]), "+f"(d[1]), "+f"(d[2]), "+f"(d[3])
        : "r"(a[0]), "r"(a[1]), "r"(a[2]), "r"(a[3]), "r"(b0), "r"(b1));
}
__device__ __forceinline__ void cpasync16(uint32_t dst, const void* src) {
    asm volatile("cp.async.cg.shared.global [%0], [%1], 16;"
                 :: "r"(dst), "l"(src) : "memory");
}
#define CP_COMMIT() asm volatile("cp.async.commit_group;" ::: "memory")
#define CP_WAIT1()  asm volatile("cp.async.wait_group 1;" ::: "memory")
#define CP_WAIT0()  asm volatile("cp.async.wait_group 0;" ::: "memory")
#define STS64(addr, val) asm volatile("st.shared.b64 [%0], %1;" :: "r"(addr), "l"(val) : "memory")

// ---------------- 1. transpose x: [B,C,H,W] -> [B,H,W,C] ----------------
__global__ void transpose_k(const float* __restrict__ x) {
    __shared__ float t[32][33];
    int b = blockIdx.z;
    int c0 = blockIdx.y * 32;
    int s0 = blockIdx.x * 32;
    int tx = threadIdx.x, ty = threadIdx.y;
    const float* xb = x + (size_t)b * CHW_;
#pragma unroll
    for (int i = 0; i < 4; ++i)
        t[ty + i*8][tx] = xb[(c0 + ty + i*8) * HW_ + s0 + tx];
    __syncthreads();
    float* xtb = g_xT + (size_t)b * CHW_;
#pragma unroll
    for (int i = 0; i < 4; ++i)
        xtb[(s0 + ty + i*8) * C_ + c0 + tx] = t[tx][ty + i*8];
}

// ------- 2a. w_def[o][c][3][3] -> bf16 hi/lo padded tiles [k][s][n=o][c] -----
__global__ void reorder_wB(const float* __restrict__ w_def) {
    int idx = blockIdx.x * 256 + threadIdx.x;
    if (idx < 9 * 128 * 128) {
        int k = idx >> 14;
        int r = idx & 16383;
        int n = r >> 7;
        int c = r & 127;
        float v = w_def[(n * C_ + c) * 9 + k];
        __nv_bfloat16 h = __float2bfloat16(v);
        float hf = __bfloat162float(h);
        __nv_bfloat16 l = __float2bfloat16(v - hf);
        g_wB[((size_t)(k * 2    ) * 128 + n) * KP + c] = h;
        g_wB[((size_t)(k * 2 + 1) * 128 + n) * KP + c] = l;
    }
}

// ---------------- 2b. reorder w_off[o][c][3][3] -> wO[c][tap][o] -------------
__global__ void reorder_wo(const float* __restrict__ w_off) {
    int idx = blockIdx.x * 256 + threadIdx.x;
    if (idx < C_ * 9 * 18) {
        int c = idx / 162;
        int r = idx - c * 162;
        int t = r / 18;
        int o = r - t * 18;
        g_wO[idx] = w_off[(o * C_ + c) * 9 + t];
    }
}

// ---------------- 3. offset conv: 3x3, 18 out, channel-split x4 --------------
__global__ void __launch_bounds__(64, 6)
offset_conv(const float* __restrict__ x, const float* __restrict__ b_off) {
    extern __shared__ float sWo[];           // 32*9*18 = 5184 floats

    const int tid = threadIdx.x;
    const int s   = blockIdx.x & 3;
    const int h0  = (blockIdx.x >> 2) * 2;
    const int b   = blockIdx.y;
    const int c0  = s * 32;

    {
        const float4* src = reinterpret_cast<const float4*>(g_wO + c0 * 162);
        float4* dst = reinterpret_cast<float4*>(sWo);
        for (int i = tid; i < 1296; i += 64) dst[i] = src[i];
    }
    __syncthreads();

    const int r  = tid >> 5;
    const int cb = tid & 31;
    const int h  = h0 + r;

    ull acc[9][4];
#pragma unroll
    for (int o9 = 0; o9 < 9; ++o9)
#pragma unroll
        for (int p = 0; p < 4; ++p) acc[o9][p] = 0ull;

    float xv[2][3][4][3];

    auto load_c = [&](int c, float v[3][4][3]) {
        const float* base = x + ((size_t)(b * C_ + c0 + c)) * HW_;
#pragma unroll
        for (int ky = 0; ky < 3; ++ky) {
            int yy = h - 1 + ky;
            bool rv = (yy >= 0 && yy < H_);
            const float* row = base + (rv ? yy : 0) * W_;
#pragma unroll
            for (int p = 0; p < 4; ++p) {
                int wc = cb + 32 * p;
                v[ky][p][0] = (rv && wc > 0)   ? __ldg(row + wc - 1) : 0.f;
                v[ky][p][1] = rv               ? __ldg(row + wc)     : 0.f;
                v[ky][p][2] = (rv && wc < 127) ? __ldg(row + wc + 1) : 0.f;
            }
        }
    };

    load_c(0, xv[0]);

    for (int c = 0; c < 32; ++c) {
        int cur = c & 1;
        if (c < 31) load_c(c + 1, xv[cur ^ 1]);
#pragma unroll
        for (int ky = 0; ky < 3; ++ky) {
#pragma unroll
            for (int kx = 0; kx < 3; ++kx) {
                const ull* wp = reinterpret_cast<const ull*>(
                    sWo + (c * 9 + ky * 3 + kx) * 18);
                ull wv[9];
#pragma unroll
                for (int o9 = 0; o9 < 9; ++o9) wv[o9] = wp[o9];
#pragma unroll
                for (int p = 0; p < 4; ++p) {
                    ull xd = packdup(xv[cur][ky][p][kx]);
#pragma unroll
                    for (int o9 = 0; o9 < 9; ++o9) ffma2(acc[o9][p], wv[o9], xd);
                }
            }
        }
    }

    float* dst = g_off + (size_t)s * PSZ;
#pragma unroll
    for (int o9 = 0; o9 < 9; ++o9) {
        float b0 = (s == 0) ? __ldg(&b_off[2 * o9])     : 0.f;
        float b1 = (s == 0) ? __ldg(&b_off[2 * o9 + 1]) : 0.f;
#pragma unroll
        for (int p = 0; p < 4; ++p) {
            float lo, hi;
            unpack2(acc[o9][p], lo, hi);
            int wc = cb + p * 32;
            dst[((b * 18 + 2 * o9    ) * H_ + h) * W_ + wc] = lo + b0;
            dst[((b * 18 + 2 * o9 + 1) * H_ + h) * W_ + wc] = hi + b1;
        }
    }
}

// ---------------- 4. main: mma.sync bf16x3 GEMM, pipelined gather ------------
// Block = one image row: M=128 positions, N=128 outputs, 256 threads / 8 warps.
// Warp tile 32(M) x 64(N). K = 9 taps x 128 channels, kchunks of 16.
// A gathered fp32 -> split bf16 hi/lo -> smem (pitch 136 bf16, bank step 4).
// B pre-split/padded in gmem, cp.async double-buffered per tap.
// B fragments via NON-trans ldmatrix: B is [n][k] with k contiguous =
// col-major k x n as required by mma row.col.
__global__ void __launch_bounds__(256, 1)
deform_main(const float* __restrict__ b_def, const float* __restrict__ w_attn,
            const float* __restrict__ b_attn, float* __restrict__ out) {
    extern __shared__ char smem[];
    const uint32_t smem_base = smem_u32(smem);
    __shared__ float sGate[128];

    const int tid  = threadIdx.x;
    const int lane = tid & 31;
    const int warp = tid >> 5;
    const int h    = blockIdx.x;
    const int b    = blockIdx.y;

    const int mband = warp & 3;      // M band: rows mband*32 .. +31
    const int nhalf = warp >> 2;     // N half: cols nhalf*64 .. +63

    const int posi8 = tid >> 3;      // gather: 0..31
    const int lane8 = tid & 7;

    const float* offbase = g_off + ((size_t)b * 18 * H_ + h) * W_;

    float acc[2][8][4];
#pragma unroll
    for (int mt = 0; mt < 2; ++mt)
#pragma unroll
        for (int n8 = 0; n8 < 8; ++n8)
#pragma unroll
            for (int i = 0; i < 4; ++i) acc[mt][n8][i] = 0.f;

    uint32_t Ah[32], Al[32];         // gathered slice: 4 pos x 8 bf16x2

    auto do_gather = [&](int k) {
        const int ky = k / 3, kx = k - 3 * ky;
#pragma unroll
        for (int p = 0; p < 4; ++p) {
            const int pos = posi8 + 32 * p;
            int oy = (2 * k) * HW_ + pos;
            int ox = oy + HW_;
            float dy = offbase[oy] + offbase[oy + PSZ] +
                       offbase[oy + 2 * PSZ] + offbase[oy + 3 * PSZ];
            float dx = offbase[ox] + offbase[ox + PSZ] +
                       offbase[ox + 2 * PSZ] + offbase[ox + 3 * PSZ];
            float ys = (float)(h   - 1 + ky) + dy;
            float xs = (float)(pos - 1 + kx) + dx;
            int y0 = __float2int_rd(ys);
            int x0 = __float2int_rd(xs);
            float wy = ys - (float)y0;
            float wx = xs - (float)x0;
            float twA[4] = {(1.f - wy) * (1.f - wx), (1.f - wy) * wx,
                            wy * (1.f - wx),          wy * wx};
            ull a[8];
#pragma unroll
            for (int j = 0; j < 8; ++j) a[j] = 0ull;
#pragma unroll
            for (int t = 0; t < 4; ++t) {
                int yy = y0 + (t >> 1);
                int xx = x0 + (t & 1);
                if (yy >= 0 && yy < H_ && xx >= 0 && xx < W_) {
                    const ulonglong2* rp = reinterpret_cast<const ulonglong2*>(
                        g_xT + (((size_t)(b * H_ + yy) * W_ + xx) << 7));
                    ull wt2 = packdup(twA[t]);
#pragma unroll
                    for (int g = 0; g < 4; ++g) {
                        ulonglong2 rr = __ldg(rp + g * 8 + lane8);
                        ffma2(a[2 * g    ], wt2, rr.x);
                        ffma2(a[2 * g + 1], wt2, rr.y);
                    }
                }
            }
#pragma unroll
            for (int j = 0; j < 8; ++j) {
                float f0, f1;
                unpack2(a[j], f0, f1);
                uint32_t hp = bf16x2_of(f0, f1);
                float h0 = __uint_as_float(hp << 16);
                float h1 = __uint_as_float(hp & 0xffff0000u);
                Ah[p * 8 + j] = hp;
                Al[p * 8 + j] = bf16x2_of(f0 - h0, f1 - h1);
            }
        }
    };

    auto sts_A = [&]() {
#pragma unroll
        for (int p = 0; p < 4; ++p) {
            const int pos = posi8 + 32 * p;
#pragma unroll
            for (int g = 0; g < 4; ++g) {
                int byte = pos * KPB + (g * 32 + lane8 * 4) * 2;
                ull hv = (ull)Ah[p * 8 + 2 * g] | ((ull)Ah[p * 8 + 2 * g + 1] << 32);
                ull lv = (ull)Al[p * 8 + 2 * g] | ((ull)Al[p * 8 + 2 * g + 1] << 32);
                STS64(smem_base + SA_HI + byte, hv);
                STS64(smem_base + SA_LO + byte, lv);
            }
        }
    };

    auto stage_B = [&](int k, int buf) {
        const char* src = (const char*)g_wB + (size_t)k * TAPB;
        uint32_t dst = smem_base + SB0 + buf * TAPB;
#pragma unroll
        for (int i = 0; i < 17; ++i) {
            int off = tid * 16 + i * 4096;
            cpasync16(dst + off, src + off);
        }
    };

    // ldmatrix per-lane address components (both operands NON-trans)
    const uint32_t aoff = (mband * 32 + (lane & 15)) * KPB + (lane >> 4) * 16;
    const uint32_t boff = (nhalf * 64 + (lane & 7) + ((lane >> 4) & 1) * 8) * KPB
                        + ((lane >> 3) & 1) * 16;

    // ---- prologue ----
    do_gather(0);
    stage_B(0, 0); CP_COMMIT();
    sts_A();
    stage_B(1, 1); CP_COMMIT();
    CP_WAIT1();
    __syncthreads();

    // ---- main pipeline over 9 taps ----
    for (int k = 0; k < 9; ++k) {
        if (k < 8) do_gather(k + 1);          // LDGs fly during mma below

        const uint32_t aHi = smem_base + SA_HI + aoff;
        const uint32_t aLo = smem_base + SA_LO + aoff;
        const uint32_t bB  = smem_base + SB0 + (k & 1) * TAPB + boff;
#pragma unroll
        for (int kc = 0; kc < 8; ++kc) {
            uint32_t ah[2][4], al[2][4];
#pragma unroll
            for (int mt = 0; mt < 2; ++mt) {
                ldmx4(ah[mt], aHi + mt * (16 * KPB) + kc * 32);
                ldmx4(al[mt], aLo + mt * (16 * KPB) + kc * 32);
            }
#pragma unroll
            for (int ng = 0; ng < 4; ++ng) {
                uint32_t bh[4], bl[4];
                uint32_t ba = bB + ng * (16 * KPB) + kc * 32;
                ldmx4(bh, ba);
                ldmx4(bl, ba + TILEB);
#pragma unroll
                for (int mt = 0; mt < 2; ++mt) {
                    mma_bf16(acc[mt][2 * ng],     ah[mt], bh[0], bh[1]);
                    mma_bf16(acc[mt][2 * ng],     al[mt], bh[0], bh[1]);
                    mma_bf16(acc[mt][2 * ng],     ah[mt], bl[0], bl[1]);
                    mma_bf16(acc[mt][2 * ng + 1], ah[mt], bh[2], bh[3]);
                    mma_bf16(acc[mt][2 * ng + 1], al[mt], bh[2], bh[3]);
                    mma_bf16(acc[mt][2 * ng + 1], ah[mt], bl[2], bl[3]);
                }
            }
        }
        __syncthreads();                      // A and B(k&1) consumed

        if (k < 8) {
            sts_A();
            if (k + 2 <= 8) { stage_B(k + 2, k & 1); CP_COMMIT(); CP_WAIT1(); }
            else            { CP_WAIT0(); }
            __syncthreads();
        }
    }

    // ---- epilogue: fragments -> stage[pos][o] (reuse A region) ----
    float* stage = (float*)smem;              // 128*132 floats = 67584 B
    const int drow = lane >> 2;
    const int dcol = (lane & 3) * 2;
#pragma unroll
    for (int mt = 0; mt < 2; ++mt) {
#pragma unroll
        for (int n8 = 0; n8 < 8; ++n8) {
            int pos = mband * 32 + mt * 16 + drow;
            int o   = nhalf * 64 + n8 * 8 + dcol;
            float2 v01 = make_float2(acc[mt][n8][0], acc[mt][n8][1]);
            float2 v23 = make_float2(acc[mt][n8][2], acc[mt][n8][3]);
            *reinterpret_cast<float2*>(stage + pos * 132 + o)       = v01;
            *reinterpret_cast<float2*>(stage + (pos + 8) * 132 + o) = v23;
        }
    }
    __syncthreads();

    // ---- bias + attention gate ----
    if (tid < 128) {
        float a = __ldg(&b_attn[0]);
        float* row = stage + tid * 132;
#pragma unroll 8
        for (int o = 0; o < 128; ++o) {
            float v = row[o] + __ldg(&b_def[o]);
            row[o] = v;
            a += v * __ldg(&w_attn[o]);
        }
        sGate[tid] = 1.f / (1.f + expf(-a));
    }
    __syncthreads();

    // ---- gate + relu + coalesced store ----
#pragma unroll
    for (int i = 0; i < 64; ++i) {
        int idx = tid + i * 256;              // 16384 elements
        int o   = idx >> 7;
        int pos = idx & 127;
        float v = stage[pos * 132 + o] * sGate[pos];
        out[(((size_t)(b * C_ + o)) * H_ + h) * W_ + pos] = fmaxf(v, 0.f);
    }
}

// ---------------- launch ----------------
extern "C" void kernel_launch(void* const* d_in, const int* in_sizes, int n_in,
                              void* d_out, int out_size) {
    const float* x      = (const float*)d_in[0];
    const float* w_off  = (const float*)d_in[1];
    const float* b_off  = (const float*)d_in[2];
    const float* w_def  = (const float*)d_in[3];
    const float* b_def  = (const float*)d_in[4];
    const float* w_attn = (const float*)d_in[5];
    const float* b_attn = (const float*)d_in[6];
    float* out = (float*)d_out;

    const int offc_smem = 5184 * 4;          // 20736 B
    cudaFuncSetAttribute(offset_conv, cudaFuncAttributeMaxDynamicSharedMemorySize, offc_smem);
    cudaFuncSetAttribute(deform_main, cudaFuncAttributeMaxDynamicSharedMemorySize, SMEMSZ);

    transpose_k<<<dim3(HW_ / 32, C_ / 32, B_), dim3(32, 8)>>>(x);
    reorder_wB<<<(9 * 128 * 128 + 255) / 256, 256>>>(w_def);
    reorder_wo<<<(C_ * 9 * 18 + 255) / 256, 256>>>(w_off);
    offset_conv<<<dim3((H_ / 2) * 4, B_), 64, offc_smem>>>(x, b_off);
    deform_main<<<dim3(H_, B_), 256, SMEMSZ>>>(b_def, w_attn, b_attn, out);
}